// round 8
// baseline (speedup 1.0000x reference)
#include <cuda_runtime.h>
#include <cstdint>

#define MAX_ROWS 16384
__device__ float  g_rowsum[MAX_ROWS];
__device__ float  g_rowsq[MAX_ROWS];
__device__ float2 g_coef[MAX_ROWS];   // per GLOBAL row: (a, b) for out = a*x + b
__device__ unsigned g_bar;            // zero-init; rolling-target barrier (replay-safe)

#define GRIDN 296                     // 2 blocks per SM on 148-SM B300 (<=2x152 on GB300)
#define TPB   512
#define WPB   16                      // warps per block
#define MAX_CACHE_BYTES 100352        // 8 rows * 784 float4 * 16B; 2 blocks/SM fit in 228KB

// ---- int32/int64 robustness: harness may deliver int64 refs as int32.
__device__ __forceinline__ bool buf_is_i64(const void* p) {
    const int* q = (const int*)p;
    return (q[1] == 0) && (q[3] == 0) && (q[5] == 0);
}
__device__ __forceinline__ long long load_i(const void* p, int i, bool is64) {
    return is64 ? ((const long long*)p)[i] : (long long)((const int*)p)[i];
}

// Rolling-target grid barrier: counter only ever increases, so it is safe
// across graph replays (each barrier instance consumes exactly GRIDN arrivals;
// all blocks are co-resident by construction).
__device__ __forceinline__ void grid_barrier() {
    __syncthreads();
    __threadfence();
    if (threadIdx.x == 0) {
        const unsigned a = atomicAdd(&g_bar, 1u);
        const unsigned target = (a / GRIDN + 1u) * GRIDN;
        while (atomicAdd(&g_bar, 0u) < target) { __nanosleep(64); }
    }
    __syncthreads();
}

__global__ void __launch_bounds__(TPB, 2) vgn_kernel(
    const float* __restrict__ x,
    float* __restrict__ out,
    const void* __restrict__ indexes,
    const float* __restrict__ weight,
    const float* __restrict__ bias,
    const void* __restrict__ group_sizes,
    int C, int G, int HW4, int NC, int NG, int cacheRows)
{
    extern __shared__ float4 s_cache[];          // cacheRows * HW4 float4
    const int wid  = threadIdx.x >> 5;
    const int lane = threadIdx.x & 31;
    const int rs = (int)(((long long)blockIdx.x       * NC) / GRIDN);
    const int re = (int)(((long long)(blockIdx.x + 1) * NC) / GRIDN);
    const int nfull = HW4 & ~255;

    // ---------------- Phase 1: row stats (+ smem-cache first cacheRows rows) --
    for (int r = rs + wid; r < re; r += WPB) {
        const float4* __restrict__ p = (const float4*)(x + (size_t)r * (size_t)(HW4 * 4));
        const int slot = r - rs;
        float s1a = 0.f, s2a = 0.f, s1b = 0.f, s2b = 0.f;
        if (slot < cacheRows) {
            float4* __restrict__ cp = s_cache + (size_t)slot * HW4;
            for (int j0 = 0; j0 < nfull; j0 += 256) {
                float4 v[8];
                #pragma unroll
                for (int k = 0; k < 8; ++k) v[k] = p[j0 + (k << 5) + lane];
                #pragma unroll
                for (int k = 0; k < 8; ++k) cp[j0 + (k << 5) + lane] = v[k];
                #pragma unroll
                for (int k = 0; k < 8; k += 2) {
                    s1a += (v[k].x + v[k].y) + (v[k].z + v[k].w);
                    s2a += v[k].x*v[k].x + v[k].y*v[k].y + v[k].z*v[k].z + v[k].w*v[k].w;
                    s1b += (v[k+1].x + v[k+1].y) + (v[k+1].z + v[k+1].w);
                    s2b += v[k+1].x*v[k+1].x + v[k+1].y*v[k+1].y
                         + v[k+1].z*v[k+1].z + v[k+1].w*v[k+1].w;
                }
            }
            for (int j = nfull + lane; j < HW4; j += 32) {
                float4 v = p[j];
                cp[j] = v;
                s1a += (v.x + v.y) + (v.z + v.w);
                s2a += v.x*v.x + v.y*v.y + v.z*v.z + v.w*v.w;
            }
        } else {
            for (int j0 = 0; j0 < nfull; j0 += 256) {
                float4 v[8];
                #pragma unroll
                for (int k = 0; k < 8; ++k) v[k] = p[j0 + (k << 5) + lane];
                #pragma unroll
                for (int k = 0; k < 8; k += 2) {
                    s1a += (v[k].x + v[k].y) + (v[k].z + v[k].w);
                    s2a += v[k].x*v[k].x + v[k].y*v[k].y + v[k].z*v[k].z + v[k].w*v[k].w;
                    s1b += (v[k+1].x + v[k+1].y) + (v[k+1].z + v[k+1].w);
                    s2b += v[k+1].x*v[k+1].x + v[k+1].y*v[k+1].y
                         + v[k+1].z*v[k+1].z + v[k+1].w*v[k+1].w;
                }
            }
            for (int j = nfull + lane; j < HW4; j += 32) {
                float4 v = p[j];
                s1a += (v.x + v.y) + (v.z + v.w);
                s2a += v.x*v.x + v.y*v.y + v.z*v.z + v.w*v.w;
            }
        }
        float s1 = s1a + s1b, s2 = s2a + s2b;
        #pragma unroll
        for (int o = 16; o; o >>= 1) {
            s1 += __shfl_down_sync(0xffffffffu, s1, o);
            s2 += __shfl_down_sync(0xffffffffu, s2, o);
        }
        if (lane == 0) { g_rowsum[r] = s1; g_rowsq[r] = s2; }
    }

    grid_barrier();

    // ---------------- Phase 2: coefficients (first NG warps of the grid) -----
    {
        const int b = blockIdx.x * WPB + wid;
        if (b < NG) {
            const int n = b / G;
            const int g = b - n * G;
            const bool gs64 = buf_is_i64(group_sizes);
            int gsz = (lane < G) ? (int)load_i(group_sizes, lane, gs64) : 0;
            int scan = gsz;
            #pragma unroll
            for (int o = 1; o < 32; o <<= 1) {
                int t = __shfl_up_sync(0xffffffffu, scan, o);
                if (lane >= o) scan += t;
            }
            const int cstart = __shfl_sync(0xffffffffu, scan - gsz, g);
            const int glen   = __shfl_sync(0xffffffffu, gsz, g);

            const bool ix64 = buf_is_i64(indexes);
            float s1 = 0.f, s2 = 0.f;
            long long myrow = -1;
            int myc = -1;
            for (int cc = lane; cc < glen; cc += 32) {   // glen <= 32: one iter
                const int i = n * C + cstart + cc;
                const long long r = load_i(indexes, i, ix64);
                s1 += g_rowsum[(int)r];
                s2 += g_rowsq[(int)r];
                myrow = r; myc = cstart + cc;
            }
            #pragma unroll
            for (int o = 16; o; o >>= 1) {
                s1 += __shfl_xor_sync(0xffffffffu, s1, o);
                s2 += __shfl_xor_sync(0xffffffffu, s2, o);
            }
            const float cnt  = (float)glen * (float)(HW4 * 4);
            const float mu   = s1 / cnt;
            const float var  = (s2 - cnt * mu * mu) / (cnt - 1.0f);
            const float ivar = rsqrtf(var + 1e-12f);
            if (myc >= 0) {
                const float a = ivar * weight[myc];
                g_coef[(int)myrow] = make_float2(a, bias[myc] - mu * a);
            }
        }
    }

    grid_barrier();

    // ---------------- Phase 3: normalize (cached rows read from smem) --------
    for (int r = rs + wid; r < re; r += WPB) {
        const float2 ab = g_coef[r];
        const float a = ab.x, bsh = ab.y;
        const int slot = r - rs;
        const size_t off = (size_t)r * (size_t)(HW4 * 4);
        float4* __restrict__ po = (float4*)(out + off);

        if (slot < cacheRows) {
            const float4* __restrict__ cp = s_cache + (size_t)slot * HW4;
            for (int j0 = 0; j0 < nfull; j0 += 256) {
                float4 v[8];
                #pragma unroll
                for (int k = 0; k < 8; ++k) v[k] = cp[j0 + (k << 5) + lane];
                #pragma unroll
                for (int k = 0; k < 8; ++k) {
                    v[k].x = fmaf(v[k].x, a, bsh);
                    v[k].y = fmaf(v[k].y, a, bsh);
                    v[k].z = fmaf(v[k].z, a, bsh);
                    v[k].w = fmaf(v[k].w, a, bsh);
                }
                #pragma unroll
                for (int k = 0; k < 8; ++k) __stcs(&po[j0 + (k << 5) + lane], v[k]);
            }
            for (int j = nfull + lane; j < HW4; j += 32) {
                float4 v = cp[j];
                v.x = fmaf(v.x, a, bsh); v.y = fmaf(v.y, a, bsh);
                v.z = fmaf(v.z, a, bsh); v.w = fmaf(v.w, a, bsh);
                __stcs(&po[j], v);
            }
        } else {
            const float4* __restrict__ px = (const float4*)(x + off);
            for (int j0 = 0; j0 < nfull; j0 += 256) {
                float4 v[8];
                #pragma unroll
                for (int k = 0; k < 8; ++k) v[k] = __ldcs(&px[j0 + (k << 5) + lane]);
                #pragma unroll
                for (int k = 0; k < 8; ++k) {
                    v[k].x = fmaf(v[k].x, a, bsh);
                    v[k].y = fmaf(v[k].y, a, bsh);
                    v[k].z = fmaf(v[k].z, a, bsh);
                    v[k].w = fmaf(v[k].w, a, bsh);
                }
                #pragma unroll
                for (int k = 0; k < 8; ++k) __stcs(&po[j0 + (k << 5) + lane], v[k]);
            }
            for (int j = nfull + lane; j < HW4; j += 32) {
                float4 v = __ldcs(&px[j]);
                v.x = fmaf(v.x, a, bsh); v.y = fmaf(v.y, a, bsh);
                v.z = fmaf(v.z, a, bsh); v.w = fmaf(v.w, a, bsh);
                __stcs(&po[j], v);
            }
        }
    }
}

extern "C" void kernel_launch(void* const* d_in, const int* in_sizes, int n_in,
                              void* d_out, int out_size)
{
    const float* x       = (const float*)d_in[0];
    const float* weight  = (const float*)d_in[1];
    const float* bias    = (const float*)d_in[2];
    const void*  gsizes  = d_in[3];
    const void*  indexes = d_in[4];
    float* out = (float*)d_out;

    const int C   = in_sizes[1];
    const int G   = in_sizes[3];
    const int NC  = in_sizes[4];
    const int HW  = in_sizes[0] / NC;
    const int HW4 = HW / 4;
    const int N   = NC / C;
    const int NG  = N * G;

    const size_t rowBytes = (size_t)HW4 * 16;
    int cacheRows = 0;
    if (rowBytes > 0) {
        size_t cr = MAX_CACHE_BYTES / rowBytes;
        cacheRows = (cr > 8) ? 8 : (int)cr;
    }
    const size_t smemBytes = (size_t)cacheRows * rowBytes;

    static int attr_done = 0;
    if (!attr_done) {
        cudaFuncSetAttribute(vgn_kernel,
                             cudaFuncAttributeMaxDynamicSharedMemorySize,
                             MAX_CACHE_BYTES);
        attr_done = 1;
    }

    vgn_kernel<<<GRIDN, TPB, smemBytes>>>(x, out, indexes, weight, bias, gsizes,
                                          C, G, HW4, NC, NG, cacheRows);
}

// round 10
// speedup vs baseline: 1.0615x; 1.0615x over previous
#include <cuda_runtime.h>
#include <cstdint>

#define MAX_ROWS 16384
__device__ float  g_rowsum[MAX_ROWS];
__device__ float  g_rowsq[MAX_ROWS];
__device__ float2 g_coef[MAX_ROWS];   // per GLOBAL row: (a, b) for out = a*x + b

// ---- int32/int64 robustness: harness may deliver int64 refs as int32.
__device__ __forceinline__ bool buf_is_i64(const void* p) {
    const int* q = (const int*)p;
    return (q[1] == 0) && (q[3] == 0) && (q[5] == 0);
}
__device__ __forceinline__ long long load_i(const void* p, int i, bool is64) {
    return is64 ? ((const long long*)p)[i] : (long long)((const int*)p)[i];
}

// 32-byte load (8 floats) with L2 evict_last policy. sm_103a ptxas only
// accepts the evict_last modifier on .v8.b32/.v4.b64 shapes.
struct f8 { float4 a, b; };
__device__ __forceinline__ f8 ldg_evict_last32(const void* p) {
    unsigned long long r0, r1, r2, r3;
    asm volatile("ld.global.L2::evict_last.v4.b64 {%0,%1,%2,%3}, [%4];"
                 : "=l"(r0), "=l"(r1), "=l"(r2), "=l"(r3) : "l"(p));
    f8 v;
    v.a.x = __uint_as_float((unsigned)r0);
    v.a.y = __uint_as_float((unsigned)(r0 >> 32));
    v.a.z = __uint_as_float((unsigned)r1);
    v.a.w = __uint_as_float((unsigned)(r1 >> 32));
    v.b.x = __uint_as_float((unsigned)r2);
    v.b.y = __uint_as_float((unsigned)(r2 >> 32));
    v.b.z = __uint_as_float((unsigned)r3);
    v.b.w = __uint_as_float((unsigned)(r3 >> 32));
    return v;
}

// ---------------- Kernel 1: per-row sum & sumsq, NATURAL order ----------------
// Warp per global row. 4 independent 32B loads in flight per lane (=128B),
// all tagged evict_last to pin x in L2 for kernel 3's re-read.
__global__ void __launch_bounds__(128) row_stats_kernel(
    const float* __restrict__ x, int HW4, int NC)
{
    const int r = (blockIdx.x << 2) + (threadIdx.x >> 5);
    if (r >= NC) return;
    const int lane = threadIdx.x & 31;
    const char* __restrict__ base = (const char*)(x + (size_t)r * (size_t)(HW4 * 4));

    const int n8 = HW4 >> 1;                     // row length in 32B units
    const int nfull8 = n8 & ~127;                // chunks of 128 float8
    float s1a = 0.f, s2a = 0.f, s1b = 0.f, s2b = 0.f;
    for (int j0 = 0; j0 < nfull8; j0 += 128) {
        f8 v[4];
        #pragma unroll
        for (int k = 0; k < 4; ++k)
            v[k] = ldg_evict_last32(base + (size_t)(j0 + (k << 5) + lane) * 32);
        #pragma unroll
        for (int k = 0; k < 4; ++k) {
            s1a += (v[k].a.x + v[k].a.y) + (v[k].a.z + v[k].a.w);
            s2a += v[k].a.x*v[k].a.x + v[k].a.y*v[k].a.y
                 + v[k].a.z*v[k].a.z + v[k].a.w*v[k].a.w;
            s1b += (v[k].b.x + v[k].b.y) + (v[k].b.z + v[k].b.w);
            s2b += v[k].b.x*v[k].b.x + v[k].b.y*v[k].b.y
                 + v[k].b.z*v[k].b.z + v[k].b.w*v[k].b.w;
        }
    }
    const float4* __restrict__ p4 = (const float4*)base;
    for (int j = (nfull8 << 1) + lane; j < HW4; j += 32) {   // short tail
        float4 v = p4[j];
        s1a += (v.x + v.y) + (v.z + v.w);
        s2a += v.x*v.x + v.y*v.y + v.z*v.z + v.w*v.w;
    }
    float s1 = s1a + s1b, s2 = s2a + s2b;
    #pragma unroll
    for (int o = 16; o; o >>= 1) {
        s1 += __shfl_down_sync(0xffffffffu, s1, o);
        s2 += __shfl_down_sync(0xffffffffu, s2, o);
    }
    if (lane == 0) { g_rowsum[r] = s1; g_rowsq[r] = s2; }
}

// ---------------- Kernel 2: group stats -> per-global-row coefficients -------
__global__ void __launch_bounds__(256) coef_kernel(
    const void* __restrict__ indexes,
    const float* __restrict__ weight,
    const float* __restrict__ bias,
    const void* __restrict__ group_sizes,
    int C, int G, int HW, int NG)
{
    const int b = (blockIdx.x << 3) + (threadIdx.x >> 5);
    if (b >= NG) return;
    const int lane = threadIdx.x & 31;
    const int n = b / G;
    const int g = b - n * G;

    const bool gs64 = buf_is_i64(group_sizes);
    int gsz = (lane < G) ? (int)load_i(group_sizes, lane, gs64) : 0;
    int scan = gsz;
    #pragma unroll
    for (int o = 1; o < 32; o <<= 1) {
        int t = __shfl_up_sync(0xffffffffu, scan, o);
        if (lane >= o) scan += t;
    }
    const int cstart = __shfl_sync(0xffffffffu, scan - gsz, g);
    const int glen   = __shfl_sync(0xffffffffu, gsz, g);

    const bool ix64 = buf_is_i64(indexes);
    float s1 = 0.f, s2 = 0.f;
    long long myrow = -1;
    int myc = -1;
    for (int cc = lane; cc < glen; cc += 32) {     // glen <= 32: one iter
        const int i = n * C + cstart + cc;
        const long long r = load_i(indexes, i, ix64);
        s1 += g_rowsum[(int)r];
        s2 += g_rowsq[(int)r];
        myrow = r; myc = cstart + cc;
    }
    #pragma unroll
    for (int o = 16; o; o >>= 1) {
        s1 += __shfl_xor_sync(0xffffffffu, s1, o);
        s2 += __shfl_xor_sync(0xffffffffu, s2, o);
    }
    const float cnt  = (float)glen * (float)HW;
    const float mu   = s1 / cnt;
    const float var  = (s2 - cnt * mu * mu) / (cnt - 1.0f);
    const float ivar = rsqrtf(var + 1e-12f);
    if (myc >= 0) {
        const float a = ivar * weight[myc];
        g_coef[(int)myrow] = make_float2(a, bias[myc] - mu * a);
    }
}

// ---------------- Kernel 3: normalize, NATURAL order, no indirection --------
// x reads should now hit in L2 (lines pinned evict_last by K1); stores stream
// out evict-first so they displace each other, not x.
__global__ void __launch_bounds__(128) normalize_kernel(
    const float* __restrict__ x,
    float* __restrict__ out,
    int HW4, int NC)
{
    const int r = (blockIdx.x << 2) + (threadIdx.x >> 5);
    if (r >= NC) return;
    const int lane = threadIdx.x & 31;
    const float2 ab = g_coef[r];                 // same addr per warp: broadcast
    const float a = ab.x, bsh = ab.y;

    const size_t off = (size_t)r * (size_t)(HW4 * 4);
    const float4* __restrict__ px = (const float4*)(x + off);
    float4*       __restrict__ po = (float4*)(out + off);

    const int nfull = HW4 & ~255;
    for (int j0 = 0; j0 < nfull; j0 += 256) {
        float4 v[8];
        #pragma unroll
        for (int k = 0; k < 8; ++k) v[k] = __ldcs(&px[j0 + (k << 5) + lane]);
        #pragma unroll
        for (int k = 0; k < 8; ++k) {
            v[k].x = fmaf(v[k].x, a, bsh);
            v[k].y = fmaf(v[k].y, a, bsh);
            v[k].z = fmaf(v[k].z, a, bsh);
            v[k].w = fmaf(v[k].w, a, bsh);
        }
        #pragma unroll
        for (int k = 0; k < 8; ++k) __stcs(&po[j0 + (k << 5) + lane], v[k]);
    }
    for (int j = nfull + lane; j < HW4; j += 32) {
        float4 v = __ldcs(&px[j]);
        v.x = fmaf(v.x, a, bsh); v.y = fmaf(v.y, a, bsh);
        v.z = fmaf(v.z, a, bsh); v.w = fmaf(v.w, a, bsh);
        __stcs(&po[j], v);
    }
}

extern "C" void kernel_launch(void* const* d_in, const int* in_sizes, int n_in,
                              void* d_out, int out_size)
{
    const float* x       = (const float*)d_in[0];
    const float* weight  = (const float*)d_in[1];
    const float* bias    = (const float*)d_in[2];
    const void*  gsizes  = d_in[3];
    const void*  indexes = d_in[4];
    float* out = (float*)d_out;

    const int C   = in_sizes[1];
    const int G   = in_sizes[3];
    const int NC  = in_sizes[4];
    const int HW  = in_sizes[0] / NC;
    const int HW4 = HW / 4;
    const int N   = NC / C;
    const int NG  = N * G;

    row_stats_kernel<<<(NC + 3) / 4, 128>>>(x, HW4, NC);
    coef_kernel<<<(NG + 7) / 8, 256>>>(indexes, weight, bias, gsizes, C, G, HW, NG);
    normalize_kernel<<<(NC + 3) / 4, 128>>>(x, out, HW4, NC);
}